// round 4
// baseline (speedup 1.0000x reference)
#include <cuda_runtime.h>
#include <math.h>

#define NB 64
#define V 256
#define F 64
#define C 64
#define ALPHA_C 0.1f
#define YSZ (NB * V * F)

// ---------------- scratch (no allocations allowed) ----------------
__device__ float g_pc[NB * 4 * V];   // colsum partials, 4 slots per column block
__device__ float g_pA[NB * 4 * V];   // sum tmp^2 partials
__device__ float g_pB[NB * 4 * V];   // sum tmp*d2 partials
__device__ float g_r[NB * V];        // 1/colsum
__device__ float g_lossP[NB];
__device__ float g_Y[3 * YSZ];       // Y0 = x@(th0-th2), Y1 = x@(-th1), Y2 = x@(2*th2)
__device__ float g_part[2 * YSZ];    // k-split partial sums of s@Y1 + (s*s)@Y2

// upper-triangle 4x4 tile enumeration (10 tiles)
__constant__ int c_IT[10] = {0, 0, 0, 0, 1, 1, 1, 2, 2, 3};
__constant__ int c_JT[10] = {0, 1, 2, 3, 1, 2, 3, 2, 3, 3};

// ---------------- kernel A: Y[m] = x @ W[m], one theta-combo per block ----------------
// Grid: (4 it, 3 m, 64 b); 256 threads.
__global__ __launch_bounds__(256) void y_gemm_kernel(
    const float* __restrict__ x, const float* __restrict__ theta) {
    __shared__ float sW[64][64];
    __shared__ float sX[64][68];  // [f][i]

    const int b = blockIdx.z, m = blockIdx.y, it = blockIdx.x;
    const int i0 = it * 64;
    const int t = threadIdx.x;
    const int tx = t & 15, ty = t >> 4;
    const float* xb = x + b * V * F;

    for (int q = t; q < 64 * 16; q += 256) {
        int f = q >> 4;
        int c4 = (q & 15) * 4;
        float4 v;
        if (m == 0) {
            float4 t0 = *(const float4*)&theta[(0 * F + f) * C + c4];
            float4 t2 = *(const float4*)&theta[(2 * F + f) * C + c4];
            v = make_float4(t0.x - t2.x, t0.y - t2.y, t0.z - t2.z, t0.w - t2.w);
        } else if (m == 1) {
            float4 t1 = *(const float4*)&theta[(1 * F + f) * C + c4];
            v = make_float4(-t1.x, -t1.y, -t1.z, -t1.w);
        } else {
            float4 t2 = *(const float4*)&theta[(2 * F + f) * C + c4];
            v = make_float4(2.f * t2.x, 2.f * t2.y, 2.f * t2.z, 2.f * t2.w);
        }
        *(float4*)&sW[f][c4] = v;
    }
    for (int q = t; q < 64 * 16; q += 256) {
        int i = q >> 4;
        int f4 = (q & 15) * 4;
        float4 v = *(const float4*)&xb[(i0 + i) * F + f4];
        sX[f4 + 0][i] = v.x;
        sX[f4 + 1][i] = v.y;
        sX[f4 + 2][i] = v.z;
        sX[f4 + 3][i] = v.w;
    }
    __syncthreads();

    float acc[4][4];
#pragma unroll
    for (int ii = 0; ii < 4; ii++)
#pragma unroll
        for (int jj = 0; jj < 4; jj++) acc[ii][jj] = 0.f;

#pragma unroll 4
    for (int k = 0; k < 64; k++) {
        float4 xa = *(const float4*)&sX[k][ty * 4];
        float4 w = *(const float4*)&sW[k][tx * 4];
        float xv[4] = {xa.x, xa.y, xa.z, xa.w};
        float wv[4] = {w.x, w.y, w.z, w.w};
#pragma unroll
        for (int ii = 0; ii < 4; ii++)
#pragma unroll
            for (int jj = 0; jj < 4; jj++)
                acc[ii][jj] = fmaf(xv[ii], wv[jj], acc[ii][jj]);
    }

    float* y = g_Y + m * YSZ + b * V * F;
#pragma unroll
    for (int ii = 0; ii < 4; ii++) {
        int row = i0 + ty * 4 + ii;
        *(float4*)&y[row * F + tx * 4] = make_float4(acc[ii][0], acc[ii][1], acc[ii][2], acc[ii][3]);
    }
}

// ---------------- stage 1: symmetric pairwise ----------------
// Grid: (10, NB); 256 threads; 64x64 (i,j) tile, mirrored for it<jt.
__global__ __launch_bounds__(256) void pairwise_kernel(
    const float* __restrict__ x, const float* __restrict__ a,
    float* __restrict__ s_out /* tmp_s written here, normalized in fused kernel */) {
    __shared__ float xi_t[F][68];  // [f][i] transposed; reused as transpose buf
    __shared__ float xj_t[F][68];
    __shared__ float a_s[F];
    __shared__ float smcJ[64], smAJ[64], smBJ[64];
    __shared__ float smcI[64], smAI[64], smBI[64];

    const int b = blockIdx.y;
    const int it = c_IT[blockIdx.x], jt = c_JT[blockIdx.x];
    const int i0 = it * 64, j0 = jt * 64;
    const int t = threadIdx.x;
    const bool offdiag = (it != jt);
    const float* xb = x + b * V * F;

    for (int e = t; e < 64 * F; e += 256) {
        int row = e >> 6;
        int f = e & 63;
        xi_t[f][row] = xb[(i0 + row) * F + f];
        xj_t[f][row] = xb[(j0 + row) * F + f];
    }
    if (t < F) a_s[t] = a[t];
    if (t < 64) {
        smcJ[t] = 0.f; smAJ[t] = 0.f; smBJ[t] = 0.f;
        smcI[t] = 0.f; smAI[t] = 0.f; smBI[t] = 0.f;
    }
    __syncthreads();

    const int tx = t & 15, ty = t >> 4;

    float sc[4][4], dd[4][4];
#pragma unroll
    for (int ii = 0; ii < 4; ii++)
#pragma unroll
        for (int jj = 0; jj < 4; jj++) { sc[ii][jj] = 0.f; dd[ii][jj] = 0.f; }

#pragma unroll 4
    for (int f = 0; f < F; f++) {
        float4 xi4 = *(const float4*)&xi_t[f][ty * 4];
        float4 xj4 = *(const float4*)&xj_t[f][tx * 4];
        float xiv[4] = {xi4.x, xi4.y, xi4.z, xi4.w};
        float xjv[4] = {xj4.x, xj4.y, xj4.z, xj4.w};
        float af = a_s[f];
#pragma unroll
        for (int ii = 0; ii < 4; ii++)
#pragma unroll
            for (int jj = 0; jj < 4; jj++) {
                float d = xiv[ii] - xjv[jj];
                sc[ii][jj] = fmaf(fabsf(d), af, sc[ii][jj]);
                dd[ii][jj] = fmaf(d, d, dd[ii][jj]);
            }
    }

    float tm[4][4];
    float cpart[4] = {0.f, 0.f, 0.f, 0.f};
    float Apart[4] = {0.f, 0.f, 0.f, 0.f};
    float Bpart[4] = {0.f, 0.f, 0.f, 0.f};
    float rc[4] = {0.f, 0.f, 0.f, 0.f};
    float rA[4] = {0.f, 0.f, 0.f, 0.f};
    float rB[4] = {0.f, 0.f, 0.f, 0.f};

    float* sb = s_out + (size_t)b * V * V;
#pragma unroll
    for (int ii = 0; ii < 4; ii++) {
#pragma unroll
        for (int jj = 0; jj < 4; jj++) {
            float tmp = __expf(-fmaxf(sc[ii][jj], 0.f));
            tm[ii][jj] = tmp;
            float t2 = tmp * tmp;
            float td = tmp * dd[ii][jj];
            cpart[jj] += tmp; Apart[jj] += t2; Bpart[jj] += td;
            rc[ii] += tmp;    rA[ii] += t2;    rB[ii] += td;
        }
        *(float4*)&sb[(i0 + ty * 4 + ii) * V + j0 + tx * 4] =
            make_float4(tm[ii][0], tm[ii][1], tm[ii][2], tm[ii][3]);
    }

#pragma unroll
    for (int jj = 0; jj < 4; jj++) {
        atomicAdd(&smcJ[tx * 4 + jj], cpart[jj]);
        atomicAdd(&smAJ[tx * 4 + jj], Apart[jj]);
        atomicAdd(&smBJ[tx * 4 + jj], Bpart[jj]);
    }
    if (offdiag) {
#pragma unroll
        for (int ii = 0; ii < 4; ii++) {
            atomicAdd(&smcI[ty * 4 + ii], rc[ii]);
            atomicAdd(&smAI[ty * 4 + ii], rA[ii]);
            atomicAdd(&smBI[ty * 4 + ii], rB[ii]);
        }
    }
    __syncthreads();

    if (t < 64) {
        int bc = (b * 4 + it) * V + j0 + t;
        g_pc[bc] = smcJ[t]; g_pA[bc] = smAJ[t]; g_pB[bc] = smBJ[t];
        if (offdiag) {
            int br = (b * 4 + jt) * V + i0 + t;
            g_pc[br] = smcI[t]; g_pA[br] = smAI[t]; g_pB[br] = smBI[t];
        }
    }

    if (offdiag) {
#pragma unroll
        for (int jj = 0; jj < 4; jj++) {
            *(float4*)&xi_t[tx * 4 + jj][ty * 4] =
                make_float4(tm[0][jj], tm[1][jj], tm[2][jj], tm[3][jj]);
        }
        __syncthreads();
        for (int e = t; e < 64 * 16; e += 256) {
            int row = e >> 4;
            int c4 = (e & 15) * 4;
            *(float4*)&sb[(j0 + row) * V + i0 + c4] = *(float4*)&xi_t[row][c4];
        }
    }
}

// ---------------- stage 2: sum 4 slots, recip, per-batch loss partial ----------------
__global__ void colstats_kernel() {
    int b = blockIdx.x;
    int j = threadIdx.x;  // 256 threads
    float cs = 0.f, A = 0.f, B = 0.f;
#pragma unroll
    for (int s = 0; s < 4; s++) {
        int idx = (b * 4 + s) * V + j;
        cs += g_pc[idx]; A += g_pA[idx]; B += g_pB[idx];
    }
    float r = 1.0f / cs;
    g_r[b * V + j] = r;
    float part = A * r * r + ALPHA_C * B * r;
    __shared__ float red[256];
    red[j] = part;
    __syncthreads();
    for (int s = 128; s > 0; s >>= 1) {
        if (j < s) red[j] += red[j + s];
        __syncthreads();
    }
    if (j == 0) g_lossP[b] = red[0];
}

// ---------------- stage 3: k-split partial GEMM + fused s normalization ----------------
// Grid: (8 = 4 i-tiles x 2 k-splits, 64 b); 256 threads; K=128 per block.
__global__ __launch_bounds__(256) void fused_gemm_kernel(float* __restrict__ s_out) {
    __shared__ float sA[64][68];   // normalized s chunk transposed [k][i]
    __shared__ float sY1[64][64];  // Y1 chunk [k][c]
    __shared__ float sY2[64][64];  // Y2 chunk [k][c]

    const int b = blockIdx.y;
    const int it = blockIdx.x & 3, ks = blockIdx.x >> 2;
    const int i0 = it * 64;
    const int t = threadIdx.x;
    const int tx = t & 15, ty = t >> 4;

    float* sb = s_out + (size_t)b * V * V;
    const float* y1 = g_Y + 1 * YSZ + b * V * F;
    const float* y2 = g_Y + 2 * YSZ + b * V * F;

    float acc[4][4];
#pragma unroll
    for (int ii = 0; ii < 4; ii++)
#pragma unroll
        for (int jj = 0; jj < 4; jj++) acc[ii][jj] = 0.f;

    for (int kc = ks * 2; kc < ks * 2 + 2; kc++) {
        int k0 = kc * 64;
        for (int q = t; q < 64 * 16; q += 256) {
            int i = q >> 4;
            int k4 = (q & 15) * 4;
            float* addr = &sb[(i0 + i) * V + k0 + k4];
            float4 v = *(const float4*)addr;
            float4 rv = *(const float4*)&g_r[b * V + k0 + k4];
            v.x *= rv.x; v.y *= rv.y; v.z *= rv.z; v.w *= rv.w;
            *(float4*)addr = v;  // write back normalized s (disjoint columns per ks)
            sA[k4 + 0][i] = v.x;
            sA[k4 + 1][i] = v.y;
            sA[k4 + 2][i] = v.z;
            sA[k4 + 3][i] = v.w;
        }
        for (int q = t; q < 64 * 16; q += 256) {
            int k = q >> 4;
            int f4 = (q & 15) * 4;
            *(float4*)&sY1[k][f4] = *(const float4*)&y1[(k0 + k) * F + f4];
            *(float4*)&sY2[k][f4] = *(const float4*)&y2[(k0 + k) * F + f4];
        }
        __syncthreads();
#pragma unroll 4
        for (int k = 0; k < 64; k++) {
            float4 a4 = *(const float4*)&sA[k][ty * 4];
            float4 b1 = *(const float4*)&sY1[k][tx * 4];
            float4 b2 = *(const float4*)&sY2[k][tx * 4];
            float av[4] = {a4.x, a4.y, a4.z, a4.w};
            float b1v[4] = {b1.x, b1.y, b1.z, b1.w};
            float b2v[4] = {b2.x, b2.y, b2.z, b2.w};
            float a2[4];
#pragma unroll
            for (int u = 0; u < 4; u++) a2[u] = av[u] * av[u];
#pragma unroll
            for (int ii = 0; ii < 4; ii++)
#pragma unroll
                for (int jj = 0; jj < 4; jj++) {
                    acc[ii][jj] = fmaf(av[ii], b1v[jj], acc[ii][jj]);
                    acc[ii][jj] = fmaf(a2[ii], b2v[jj], acc[ii][jj]);
                }
        }
        __syncthreads();
    }

    float* p = g_part + ks * YSZ + b * V * F;
#pragma unroll
    for (int ii = 0; ii < 4; ii++) {
        int row = i0 + ty * 4 + ii;
        *(float4*)&p[row * F + tx * 4] = make_float4(acc[ii][0], acc[ii][1], acc[ii][2], acc[ii][3]);
    }
}

// ---------------- stage 4: gcn = relu(Y0 + P0 + P1), final loss ----------------
__global__ void epilogue_kernel(float* __restrict__ gcn, float* __restrict__ out_loss) {
    int idx = blockIdx.x * 256 + threadIdx.x;  // float4 index, total YSZ/4
    if (idx == 0) {
        float acc = 0.f;
#pragma unroll
        for (int i = 0; i < NB; i++) acc += g_lossP[i];
        *out_loss = acc;
    }
    float4 y = ((const float4*)g_Y)[idx];
    float4 p0 = ((const float4*)g_part)[idx];
    float4 p1 = ((const float4*)(g_part + YSZ))[idx];
    float4 o = make_float4(fmaxf(y.x + p0.x + p1.x, 0.f),
                           fmaxf(y.y + p0.y + p1.y, 0.f),
                           fmaxf(y.z + p0.z + p1.z, 0.f),
                           fmaxf(y.w + p0.w + p1.w, 0.f));
    ((float4*)gcn)[idx] = o;
}

// ---------------- launch ----------------
extern "C" void kernel_launch(void* const* d_in, const int* in_sizes, int n_in,
                              void* d_out, int out_size) {
    const float* x = (const float*)d_in[0];      // (64,256,64)
    const float* a = (const float*)d_in[1];      // (64,)
    const float* theta = (const float*)d_in[2];  // (3,64,64)

    float* out = (float*)d_out;
    float* gcn = out;                                 // NB*V*C
    float* s_out = out + (size_t)NB * V * C;          // NB*V*V
    float* loss = out + (size_t)NB * V * C + (size_t)NB * V * V;  // 1

    dim3 gA(4, 3, NB);
    y_gemm_kernel<<<gA, 256>>>(x, theta);

    dim3 g1(10, NB);
    pairwise_kernel<<<g1, 256>>>(x, a, s_out);

    colstats_kernel<<<NB, 256>>>();

    dim3 gB(8, NB);
    fused_gemm_kernel<<<gB, 256>>>(s_out);

    epilogue_kernel<<<YSZ / 4 / 256, 256>>>(gcn, loss);
}

// round 5
// speedup vs baseline: 1.1283x; 1.1283x over previous
#include <cuda_runtime.h>
#include <math.h>

#define NB 64
#define V 256
#define F 64
#define C 64
#define ALPHA_C 0.1f
#define YSZ (NB * V * F)

// ---------------- scratch (no allocations allowed) ----------------
__device__ float g_pc[NB * 4 * V];   // colsum partials, 4 slots per column block
__device__ float g_pA[NB * 4 * V];   // sum tmp^2 partials
__device__ float g_pB[NB * 4 * V];   // sum tmp*d2 partials
__device__ float g_lossP[NB * 2];    // per (b, ks) loss partials
__device__ float g_Y[3 * YSZ];       // Y0 = x@(th0-th2), Y1 = x@(-th1), Y2 = x@(2*th2)
__device__ float g_part[2 * YSZ];    // k-split partial sums of s@Y1 + (s*s)@Y2

// upper-triangle 4x4 tile enumeration (10 tiles)
__constant__ int c_IT[10] = {0, 0, 0, 0, 1, 1, 1, 2, 2, 3};
__constant__ int c_JT[10] = {0, 1, 2, 3, 1, 2, 3, 2, 3, 3};

#define N_PW 640   // pairwise blocks: 10 tiles x 64 b
#define N_YG 768   // y-gemm blocks: 4 it x 3 m x 64 b

// ---------------- mega kernel 1: pairwise (idx<640) + y_gemm (idx>=640) ----------------
__global__ __launch_bounds__(256) void mega1_kernel(
    const float* __restrict__ x, const float* __restrict__ a,
    const float* __restrict__ theta, float* __restrict__ s_out) {
    __shared__ __align__(16) float pool[9152];  // union: pairwise 9152f, y 8448f

    const int t = threadIdx.x;
    const int tx = t & 15, ty = t >> 4;

    if (blockIdx.x >= N_PW) {
        // ================= y_gemm part =================
        int idx = blockIdx.x - N_PW;
        const int it = idx & 3;
        const int m = (idx >> 2) % 3;
        const int b = idx / 12;
        const int i0 = it * 64;
        float (*sW)[64] = (float(*)[64])pool;          // 4096
        float (*sX)[68] = (float(*)[68])(pool + 4096); // 4352
        const float* xb = x + b * V * F;

        for (int q = t; q < 64 * 16; q += 256) {
            int f = q >> 4;
            int c4 = (q & 15) * 4;
            float4 v;
            if (m == 0) {
                float4 t0 = *(const float4*)&theta[(0 * F + f) * C + c4];
                float4 t2 = *(const float4*)&theta[(2 * F + f) * C + c4];
                v = make_float4(t0.x - t2.x, t0.y - t2.y, t0.z - t2.z, t0.w - t2.w);
            } else if (m == 1) {
                float4 t1 = *(const float4*)&theta[(1 * F + f) * C + c4];
                v = make_float4(-t1.x, -t1.y, -t1.z, -t1.w);
            } else {
                float4 t2 = *(const float4*)&theta[(2 * F + f) * C + c4];
                v = make_float4(2.f * t2.x, 2.f * t2.y, 2.f * t2.z, 2.f * t2.w);
            }
            *(float4*)&sW[f][c4] = v;
        }
        for (int q = t; q < 64 * 16; q += 256) {
            int i = q >> 4;
            int f4 = (q & 15) * 4;
            float4 v = *(const float4*)&xb[(i0 + i) * F + f4];
            sX[f4 + 0][i] = v.x;
            sX[f4 + 1][i] = v.y;
            sX[f4 + 2][i] = v.z;
            sX[f4 + 3][i] = v.w;
        }
        __syncthreads();

        float acc[4][4];
#pragma unroll
        for (int ii = 0; ii < 4; ii++)
#pragma unroll
            for (int jj = 0; jj < 4; jj++) acc[ii][jj] = 0.f;

#pragma unroll 4
        for (int k = 0; k < 64; k++) {
            float4 xa = *(const float4*)&sX[k][ty * 4];
            float4 w = *(const float4*)&sW[k][tx * 4];
            float xv[4] = {xa.x, xa.y, xa.z, xa.w};
            float wv[4] = {w.x, w.y, w.z, w.w};
#pragma unroll
            for (int ii = 0; ii < 4; ii++)
#pragma unroll
                for (int jj = 0; jj < 4; jj++)
                    acc[ii][jj] = fmaf(xv[ii], wv[jj], acc[ii][jj]);
        }

        float* y = g_Y + m * YSZ + b * V * F;
#pragma unroll
        for (int ii = 0; ii < 4; ii++) {
            int row = i0 + ty * 4 + ii;
            *(float4*)&y[row * F + tx * 4] =
                make_float4(acc[ii][0], acc[ii][1], acc[ii][2], acc[ii][3]);
        }
        return;
    }

    // ================= pairwise part =================
    const int b = blockIdx.x / 10;
    const int tile = blockIdx.x % 10;
    const int it = c_IT[tile], jt = c_JT[tile];
    const int i0 = it * 64, j0 = jt * 64;
    const bool offdiag = (it != jt);
    const float* xb = x + b * V * F;

    float (*xi_t)[68] = (float(*)[68])pool;           // 4352
    float (*xj_t)[68] = (float(*)[68])(pool + 4352);  // 4352
    float* a_s = pool + 8704;                         // 64
    float* smcJ = pool + 8768;
    float* smAJ = pool + 8832;
    float* smBJ = pool + 8896;
    float* smcI = pool + 8960;
    float* smAI = pool + 9024;
    float* smBI = pool + 9088;

    for (int e = t; e < 64 * F; e += 256) {
        int row = e >> 6;
        int f = e & 63;
        xi_t[f][row] = xb[(i0 + row) * F + f];
        xj_t[f][row] = xb[(j0 + row) * F + f];
    }
    if (t < F) a_s[t] = a[t];
    if (t < 64) {
        smcJ[t] = 0.f; smAJ[t] = 0.f; smBJ[t] = 0.f;
        smcI[t] = 0.f; smAI[t] = 0.f; smBI[t] = 0.f;
    }
    __syncthreads();

    float sc[4][4], dd[4][4];
#pragma unroll
    for (int ii = 0; ii < 4; ii++)
#pragma unroll
        for (int jj = 0; jj < 4; jj++) { sc[ii][jj] = 0.f; dd[ii][jj] = 0.f; }

#pragma unroll 4
    for (int f = 0; f < F; f++) {
        float4 xi4 = *(const float4*)&xi_t[f][ty * 4];
        float4 xj4 = *(const float4*)&xj_t[f][tx * 4];
        float xiv[4] = {xi4.x, xi4.y, xi4.z, xi4.w};
        float xjv[4] = {xj4.x, xj4.y, xj4.z, xj4.w};
        float af = a_s[f];
#pragma unroll
        for (int ii = 0; ii < 4; ii++)
#pragma unroll
            for (int jj = 0; jj < 4; jj++) {
                float d = xiv[ii] - xjv[jj];
                sc[ii][jj] = fmaf(fabsf(d), af, sc[ii][jj]);
                dd[ii][jj] = fmaf(d, d, dd[ii][jj]);
            }
    }

    float tm[4][4];
    float cpart[4] = {0.f, 0.f, 0.f, 0.f};
    float Apart[4] = {0.f, 0.f, 0.f, 0.f};
    float Bpart[4] = {0.f, 0.f, 0.f, 0.f};
    float rc[4] = {0.f, 0.f, 0.f, 0.f};
    float rA[4] = {0.f, 0.f, 0.f, 0.f};
    float rB[4] = {0.f, 0.f, 0.f, 0.f};

    float* sb = s_out + (size_t)b * V * V;
#pragma unroll
    for (int ii = 0; ii < 4; ii++) {
#pragma unroll
        for (int jj = 0; jj < 4; jj++) {
            float tmp = __expf(-fmaxf(sc[ii][jj], 0.f));
            tm[ii][jj] = tmp;
            float t2 = tmp * tmp;
            float td = tmp * dd[ii][jj];
            cpart[jj] += tmp; Apart[jj] += t2; Bpart[jj] += td;
            rc[ii] += tmp;    rA[ii] += t2;    rB[ii] += td;
        }
        *(float4*)&sb[(i0 + ty * 4 + ii) * V + j0 + tx * 4] =
            make_float4(tm[ii][0], tm[ii][1], tm[ii][2], tm[ii][3]);
    }

#pragma unroll
    for (int jj = 0; jj < 4; jj++) {
        atomicAdd(&smcJ[tx * 4 + jj], cpart[jj]);
        atomicAdd(&smAJ[tx * 4 + jj], Apart[jj]);
        atomicAdd(&smBJ[tx * 4 + jj], Bpart[jj]);
    }
    if (offdiag) {
#pragma unroll
        for (int ii = 0; ii < 4; ii++) {
            atomicAdd(&smcI[ty * 4 + ii], rc[ii]);
            atomicAdd(&smAI[ty * 4 + ii], rA[ii]);
            atomicAdd(&smBI[ty * 4 + ii], rB[ii]);
        }
    }
    __syncthreads();

    if (t < 64) {
        int bc = (b * 4 + it) * V + j0 + t;
        g_pc[bc] = smcJ[t]; g_pA[bc] = smAJ[t]; g_pB[bc] = smBJ[t];
        if (offdiag) {
            int br = (b * 4 + jt) * V + i0 + t;
            g_pc[br] = smcI[t]; g_pA[br] = smAI[t]; g_pB[br] = smBI[t];
        }
    }

    if (offdiag) {
#pragma unroll
        for (int jj = 0; jj < 4; jj++) {
            *(float4*)&xi_t[tx * 4 + jj][ty * 4] =
                make_float4(tm[0][jj], tm[1][jj], tm[2][jj], tm[3][jj]);
        }
        __syncthreads();
        for (int e = t; e < 64 * 16; e += 256) {
            int row = e >> 4;
            int c4 = (e & 15) * 4;
            *(float4*)&sb[(j0 + row) * V + i0 + c4] = *(float4*)&xi_t[row][c4];
        }
    }
}

// ---------------- stage 2: k-split GEMM + local r + fused normalization + loss ----------------
// Grid: (8 = 4 i-tiles x 2 k-splits, 64 b); 256 threads; K=128 per block.
__global__ __launch_bounds__(256) void fused_gemm_kernel(float* __restrict__ s_out) {
    __shared__ __align__(16) float sA[64][68];   // normalized s chunk transposed [k][i]
    __shared__ __align__(16) float sY1[64][64];  // Y1 chunk [k][c]
    __shared__ __align__(16) float sY2[64][64];  // Y2 chunk [k][c]
    __shared__ __align__(16) float sR[128];      // 1/colsum for this block's k range

    const int b = blockIdx.y;
    const int it = blockIdx.x & 3, ks = blockIdx.x >> 2;
    const int i0 = it * 64;
    const int t = threadIdx.x;
    const int tx = t & 15, ty = t >> 4;

    // local column stats: r for cols [ks*128, ks*128+128)
    float part = 0.f;
    if (t < 128) {
        int col = ks * 128 + t;
        int base = b * 4 * V + col;
        float cs = g_pc[base] + g_pc[base + V] + g_pc[base + 2 * V] + g_pc[base + 3 * V];
        float r = 1.0f / cs;
        sR[t] = r;
        if (it == 0) {
            float A = g_pA[base] + g_pA[base + V] + g_pA[base + 2 * V] + g_pA[base + 3 * V];
            float B = g_pB[base] + g_pB[base + V] + g_pB[base + 2 * V] + g_pB[base + 3 * V];
            part = A * r * r + ALPHA_C * B * r;
        }
    }
    if (it == 0) {
        float* red = (float*)sY1;  // reuse before staging
        if (t < 128) red[t] = part;
        __syncthreads();
        for (int s = 64; s > 0; s >>= 1) {
            if (t < s) red[t] += red[t + s];
            __syncthreads();
        }
        if (t == 0) g_lossP[b * 2 + ks] = red[0];
    }
    __syncthreads();  // sR visible (and red reuse done)

    float* sb = s_out + (size_t)b * V * V;
    const float* y1 = g_Y + 1 * YSZ + b * V * F;
    const float* y2 = g_Y + 2 * YSZ + b * V * F;

    float acc[4][4];
#pragma unroll
    for (int ii = 0; ii < 4; ii++)
#pragma unroll
        for (int jj = 0; jj < 4; jj++) acc[ii][jj] = 0.f;

    for (int kc = ks * 2; kc < ks * 2 + 2; kc++) {
        int k0 = kc * 64;
        int kl = (kc - ks * 2) * 64;  // local offset into sR
        for (int q = t; q < 64 * 16; q += 256) {
            int i = q >> 4;
            int k4 = (q & 15) * 4;
            float* addr = &sb[(i0 + i) * V + k0 + k4];
            float4 v = *(const float4*)addr;
            float4 rv = *(const float4*)&sR[kl + k4];
            v.x *= rv.x; v.y *= rv.y; v.z *= rv.z; v.w *= rv.w;
            *(float4*)addr = v;  // write back normalized s (disjoint columns per ks)
            sA[k4 + 0][i] = v.x;
            sA[k4 + 1][i] = v.y;
            sA[k4 + 2][i] = v.z;
            sA[k4 + 3][i] = v.w;
        }
        for (int q = t; q < 64 * 16; q += 256) {
            int k = q >> 4;
            int f4 = (q & 15) * 4;
            *(float4*)&sY1[k][f4] = *(const float4*)&y1[(k0 + k) * F + f4];
            *(float4*)&sY2[k][f4] = *(const float4*)&y2[(k0 + k) * F + f4];
        }
        __syncthreads();
#pragma unroll 4
        for (int k = 0; k < 64; k++) {
            float4 a4 = *(const float4*)&sA[k][ty * 4];
            float4 b1 = *(const float4*)&sY1[k][tx * 4];
            float4 b2 = *(const float4*)&sY2[k][tx * 4];
            float av[4] = {a4.x, a4.y, a4.z, a4.w};
            float b1v[4] = {b1.x, b1.y, b1.z, b1.w};
            float b2v[4] = {b2.x, b2.y, b2.z, b2.w};
            float a2[4];
#pragma unroll
            for (int u = 0; u < 4; u++) a2[u] = av[u] * av[u];
#pragma unroll
            for (int ii = 0; ii < 4; ii++)
#pragma unroll
                for (int jj = 0; jj < 4; jj++) {
                    acc[ii][jj] = fmaf(av[ii], b1v[jj], acc[ii][jj]);
                    acc[ii][jj] = fmaf(a2[ii], b2v[jj], acc[ii][jj]);
                }
        }
        __syncthreads();
    }

    float* p = g_part + ks * YSZ + b * V * F;
#pragma unroll
    for (int ii = 0; ii < 4; ii++) {
        int row = i0 + ty * 4 + ii;
        *(float4*)&p[row * F + tx * 4] =
            make_float4(acc[ii][0], acc[ii][1], acc[ii][2], acc[ii][3]);
    }
}

// ---------------- stage 3: gcn = relu(Y0 + P0 + P1), final loss ----------------
__global__ void epilogue_kernel(float* __restrict__ gcn, float* __restrict__ out_loss) {
    int idx = blockIdx.x * 256 + threadIdx.x;  // float4 index, total YSZ/4
    if (idx == 0) {
        float acc = 0.f;
#pragma unroll
        for (int i = 0; i < NB * 2; i++) acc += g_lossP[i];
        *out_loss = acc;
    }
    float4 y = ((const float4*)g_Y)[idx];
    float4 p0 = ((const float4*)g_part)[idx];
    float4 p1 = ((const float4*)(g_part + YSZ))[idx];
    float4 o = make_float4(fmaxf(y.x + p0.x + p1.x, 0.f),
                           fmaxf(y.y + p0.y + p1.y, 0.f),
                           fmaxf(y.z + p0.z + p1.z, 0.f),
                           fmaxf(y.w + p0.w + p1.w, 0.f));
    ((float4*)gcn)[idx] = o;
}

// ---------------- launch ----------------
extern "C" void kernel_launch(void* const* d_in, const int* in_sizes, int n_in,
                              void* d_out, int out_size) {
    const float* x = (const float*)d_in[0];      // (64,256,64)
    const float* a = (const float*)d_in[1];      // (64,)
    const float* theta = (const float*)d_in[2];  // (3,64,64)

    float* out = (float*)d_out;
    float* gcn = out;                                 // NB*V*C
    float* s_out = out + (size_t)NB * V * C;          // NB*V*V
    float* loss = out + (size_t)NB * V * C + (size_t)NB * V * V;  // 1

    mega1_kernel<<<N_PW + N_YG, 256>>>(x, a, theta, s_out);

    dim3 gB(8, NB);
    fused_gemm_kernel<<<gB, 256>>>(s_out);

    epilogue_kernel<<<YSZ / 4 / 256, 256>>>(gcn, loss);
}

// round 7
// speedup vs baseline: 1.3049x; 1.1565x over previous
#include <cuda_runtime.h>
#include <math.h>

#define NB 64
#define V 256
#define F 64
#define C 64
#define ALPHA_C 0.1f
#define YSZ (NB * V * F)

// ---------------- scratch (no allocations allowed) ----------------
__device__ float g_pc[NB * 4 * V];   // colsum partials, 4 slots per column block
__device__ float g_pA[NB * 4 * V];   // sum tmp^2 partials
__device__ float g_pB[NB * 4 * V];   // sum tmp*d2 partials
__device__ float g_lossP[NB * 4];    // per (b, ks) loss partials
__device__ float g_Y[3 * YSZ];       // Y0 = x@(th0-th2), Y1 = x@(-th1), Y2 = x@(2*th2)
__device__ float g_part[4 * YSZ];    // k-split partial sums of s@Y1 + (s*s)@Y2

// upper-triangle 4x4 tile enumeration (10 tiles)
__constant__ int c_IT[10] = {0, 0, 0, 0, 1, 1, 1, 2, 2, 3};
__constant__ int c_JT[10] = {0, 1, 2, 3, 1, 2, 3, 2, 3, 3};

#define N_PW 640   // pairwise blocks: 10 tiles x 64 b
#define N_YG 768   // y-gemm blocks: 4 it x 3 m x 64 b

#define POOL_F 10880  // floats: pairwise 4352(xi)+6528(partials over xj/a_s); y path 8448

// partial-array offsets (overlay xj region, each 64*17=1088 floats)
#define P_CC 4352
#define P_AC (4352 + 1088)
#define P_BC (4352 + 2176)
#define P_CR (4352 + 3264)
#define P_AR (4352 + 4352)
#define P_BR (4352 + 5440)

// ---------------- mega kernel 1: pairwise (idx<640) + y_gemm (idx>=640) ----------------
__global__ __launch_bounds__(256) void mega1_kernel(
    const float* __restrict__ x, const float* __restrict__ a,
    const float* __restrict__ theta, float* __restrict__ s_out) {
    __shared__ __align__(16) float pool[POOL_F];

    const int t = threadIdx.x;
    const int tx = t & 15, ty = t >> 4;

    if (blockIdx.x >= N_PW) {
        // ================= y_gemm part =================
        int idx = blockIdx.x - N_PW;
        const int it = idx & 3;
        const int m = (idx >> 2) % 3;
        const int b = idx / 12;
        const int i0 = it * 64;
        float (*sW)[64] = (float(*)[64])pool;          // 4096
        float (*sX)[68] = (float(*)[68])(pool + 4096); // 4352
        const float* xb = x + b * V * F;

        for (int q = t; q < 64 * 16; q += 256) {
            int f = q >> 4;
            int c4 = (q & 15) * 4;
            float4 v;
            if (m == 0) {
                float4 t0 = *(const float4*)&theta[(0 * F + f) * C + c4];
                float4 t2 = *(const float4*)&theta[(2 * F + f) * C + c4];
                v = make_float4(t0.x - t2.x, t0.y - t2.y, t0.z - t2.z, t0.w - t2.w);
            } else if (m == 1) {
                float4 t1 = *(const float4*)&theta[(1 * F + f) * C + c4];
                v = make_float4(-t1.x, -t1.y, -t1.z, -t1.w);
            } else {
                float4 t2 = *(const float4*)&theta[(2 * F + f) * C + c4];
                v = make_float4(2.f * t2.x, 2.f * t2.y, 2.f * t2.z, 2.f * t2.w);
            }
            *(float4*)&sW[f][c4] = v;
        }
        for (int q = t; q < 64 * 16; q += 256) {
            int i = q >> 4;
            int f4 = (q & 15) * 4;
            float4 v = *(const float4*)&xb[(i0 + i) * F + f4];
            sX[f4 + 0][i] = v.x;
            sX[f4 + 1][i] = v.y;
            sX[f4 + 2][i] = v.z;
            sX[f4 + 3][i] = v.w;
        }
        __syncthreads();

        float acc[4][4];
#pragma unroll
        for (int ii = 0; ii < 4; ii++)
#pragma unroll
            for (int jj = 0; jj < 4; jj++) acc[ii][jj] = 0.f;

#pragma unroll 4
        for (int k = 0; k < 64; k++) {
            float4 xa = *(const float4*)&sX[k][ty * 4];
            float4 w = *(const float4*)&sW[k][tx * 4];
            float xv[4] = {xa.x, xa.y, xa.z, xa.w};
            float wv[4] = {w.x, w.y, w.z, w.w};
#pragma unroll
            for (int ii = 0; ii < 4; ii++)
#pragma unroll
                for (int jj = 0; jj < 4; jj++)
                    acc[ii][jj] = fmaf(xv[ii], wv[jj], acc[ii][jj]);
        }

        float* y = g_Y + m * YSZ + b * V * F;
#pragma unroll
        for (int ii = 0; ii < 4; ii++) {
            int row = i0 + ty * 4 + ii;
            *(float4*)&y[row * F + tx * 4] =
                make_float4(acc[ii][0], acc[ii][1], acc[ii][2], acc[ii][3]);
        }
        return;
    }

    // ================= pairwise part =================
    const int b = blockIdx.x / 10;
    const int tile = blockIdx.x % 10;
    const int it = c_IT[tile], jt = c_JT[tile];
    const int i0 = it * 64, j0 = jt * 64;
    const bool offdiag = (it != jt);
    const float* xb = x + b * V * F;

    float (*xi_t)[68] = (float(*)[68])pool;           // 4352
    float (*xj_t)[68] = (float(*)[68])(pool + 4352);  // 4352
    float* a_s = pool + 8704;                         // 64 (dead after main loop)

    for (int e = t; e < 64 * F; e += 256) {
        int row = e >> 6;
        int f = e & 63;
        xi_t[f][row] = xb[(i0 + row) * F + f];
        xj_t[f][row] = xb[(j0 + row) * F + f];
    }
    if (t < F) a_s[t] = a[t];
    __syncthreads();

    float sc[4][4], dd[4][4];
#pragma unroll
    for (int ii = 0; ii < 4; ii++)
#pragma unroll
        for (int jj = 0; jj < 4; jj++) { sc[ii][jj] = 0.f; dd[ii][jj] = 0.f; }

#pragma unroll 4
    for (int f = 0; f < F; f++) {
        float4 xi4 = *(const float4*)&xi_t[f][ty * 4];
        float4 xj4 = *(const float4*)&xj_t[f][tx * 4];
        float xiv[4] = {xi4.x, xi4.y, xi4.z, xi4.w};
        float xjv[4] = {xj4.x, xj4.y, xj4.z, xj4.w};
        float af = a_s[f];
#pragma unroll
        for (int ii = 0; ii < 4; ii++)
#pragma unroll
            for (int jj = 0; jj < 4; jj++) {
                float d = xiv[ii] - xjv[jj];
                sc[ii][jj] = fmaf(fabsf(d), af, sc[ii][jj]);
                dd[ii][jj] = fmaf(d, d, dd[ii][jj]);
            }
    }

    float tm[4][4];
    float cpart[4] = {0.f, 0.f, 0.f, 0.f};
    float Apart[4] = {0.f, 0.f, 0.f, 0.f};
    float Bpart[4] = {0.f, 0.f, 0.f, 0.f};
    float rc[4] = {0.f, 0.f, 0.f, 0.f};
    float rA[4] = {0.f, 0.f, 0.f, 0.f};
    float rB[4] = {0.f, 0.f, 0.f, 0.f};

#pragma unroll
    for (int ii = 0; ii < 4; ii++) {
#pragma unroll
        for (int jj = 0; jj < 4; jj++) {
            float tmp = __expf(-fmaxf(sc[ii][jj], 0.f));
            tm[ii][jj] = tmp;
            float t2 = tmp * tmp;
            float td = tmp * dd[ii][jj];
            cpart[jj] += tmp; Apart[jj] += t2; Bpart[jj] += td;
            rc[ii] += tmp;    rA[ii] += t2;    rB[ii] += td;
        }
    }

    __syncthreads();  // xi/xj/a_s reads complete; safe to overlay

    float* sb = s_out + (size_t)b * V * V;
#pragma unroll
    for (int ii = 0; ii < 4; ii++) {
        *(float4*)&sb[(i0 + ty * 4 + ii) * V + j0 + tx * 4] =
            make_float4(tm[ii][0], tm[ii][1], tm[ii][2], tm[ii][3]);
    }

    // non-atomic partial stores: [col][ty] / [row][tx], pad 17 (all scalar)
#pragma unroll
    for (int jj = 0; jj < 4; jj++) {
        int col = tx * 4 + jj;
        pool[P_CC + col * 17 + ty] = cpart[jj];
        pool[P_AC + col * 17 + ty] = Apart[jj];
        pool[P_BC + col * 17 + ty] = Bpart[jj];
    }
    if (offdiag) {
#pragma unroll
        for (int ii = 0; ii < 4; ii++) {
            int row = ty * 4 + ii;
            pool[P_CR + row * 17 + tx] = rc[ii];
            pool[P_AR + row * 17 + tx] = rA[ii];
            pool[P_BR + row * 17 + tx] = rB[ii];
        }
        // transpose tm into xi region for the mirror write
#pragma unroll
        for (int jj = 0; jj < 4; jj++) {
            *(float4*)&xi_t[tx * 4 + jj][ty * 4] =
                make_float4(tm[0][jj], tm[1][jj], tm[2][jj], tm[3][jj]);
        }
    }
    __syncthreads();

    if (t < 64) {
        float cs = 0.f, As = 0.f, Bs = 0.f;
#pragma unroll
        for (int u = 0; u < 16; u++) {
            cs += pool[P_CC + t * 17 + u];
            As += pool[P_AC + t * 17 + u];
            Bs += pool[P_BC + t * 17 + u];
        }
        int bc = (b * 4 + it) * V + j0 + t;
        g_pc[bc] = cs; g_pA[bc] = As; g_pB[bc] = Bs;
        if (offdiag) {
            float cr = 0.f, Ar = 0.f, Br = 0.f;
#pragma unroll
            for (int u = 0; u < 16; u++) {
                cr += pool[P_CR + t * 17 + u];
                Ar += pool[P_AR + t * 17 + u];
                Br += pool[P_BR + t * 17 + u];
            }
            int br = (b * 4 + jt) * V + i0 + t;
            g_pc[br] = cr; g_pA[br] = Ar; g_pB[br] = Br;
        }
    }

    if (offdiag) {
        for (int e = t; e < 64 * 16; e += 256) {
            int row = e >> 4;
            int c4 = (e & 15) * 4;
            *(float4*)&sb[(j0 + row) * V + i0 + c4] = *(float4*)&xi_t[row][c4];
        }
    }
}

// ---------------- stage 2: k-split GEMM (8x4 tiles) + local r + normalization + loss ----------------
// Grid: (8 = 2 i-tiles x 4 k-splits, 64 b); 256 threads (16tx x 16ty);
// block tile 128(i) x 64(c), K=64 per block (2 chunks of 32), 8x4 per thread.
// sA natural layout [i][k] pad 36 -> 144B rows, all float4 accesses 16B-aligned.
__global__ __launch_bounds__(256) void fused_gemm_kernel(float* __restrict__ s_out) {
    __shared__ __align__(16) float sA[128][36];  // [i][k] normalized s chunk
    __shared__ __align__(16) float sY1[32][64];  // Y1 chunk [k][c]
    __shared__ __align__(16) float sY2[32][64];  // Y2 chunk [k][c]
    __shared__ __align__(16) float sR[64];       // 1/colsum for this block's 64 k-cols

    const int b = blockIdx.y;
    const int it = blockIdx.x & 1, ks = blockIdx.x >> 1;
    const int i0 = it * 128;
    const int t = threadIdx.x;
    const int tx = t & 15, ty = t >> 4;

    // local column stats: r for cols [ks*64, ks*64+64)
    if (t < 64) {
        int base = b * 4 * V + ks * 64 + t;
        float cs = g_pc[base] + g_pc[base + V] + g_pc[base + 2 * V] + g_pc[base + 3 * V];
        sR[t] = 1.0f / cs;
    }
    if (it == 0) {  // uniform branch per block
        float* red = (float*)sY1;  // scratch before staging
        if (t < 64) {
            int base = b * 4 * V + ks * 64 + t;
            float cs = g_pc[base] + g_pc[base + V] + g_pc[base + 2 * V] + g_pc[base + 3 * V];
            float A = g_pA[base] + g_pA[base + V] + g_pA[base + 2 * V] + g_pA[base + 3 * V];
            float B = g_pB[base] + g_pB[base + V] + g_pB[base + 2 * V] + g_pB[base + 3 * V];
            float r = 1.0f / cs;
            red[t] = A * r * r + ALPHA_C * B * r;
        }
        __syncthreads();
        for (int s = 32; s > 0; s >>= 1) {
            if (t < s) red[t] += red[t + s];
            __syncthreads();
        }
        if (t == 0) g_lossP[b * 4 + ks] = red[0];
    }
    __syncthreads();

    float* sb = s_out + (size_t)b * V * V;
    const float* y1 = g_Y + 1 * YSZ + b * V * F;
    const float* y2 = g_Y + 2 * YSZ + b * V * F;

    float acc[8][4];
#pragma unroll
    for (int ii = 0; ii < 8; ii++)
#pragma unroll
        for (int jj = 0; jj < 4; jj++) acc[ii][jj] = 0.f;

    for (int chunk = 0; chunk < 2; chunk++) {
        int k0 = ks * 64 + chunk * 32;  // global col
        int cl = chunk * 32;            // local col offset into sR
        // stage s (normalize + write back), natural [i][k]
        for (int q = t; q < 128 * 8; q += 256) {
            int i = q >> 3;
            int k4 = (q & 7) * 4;
            float* addr = &sb[(i0 + i) * V + k0 + k4];
            float4 v = *(const float4*)addr;
            float4 rv = *(const float4*)&sR[cl + k4];
            v.x *= rv.x; v.y *= rv.y; v.z *= rv.z; v.w *= rv.w;
            *(float4*)addr = v;  // write back normalized s (disjoint cols per ks)
            *(float4*)&sA[i][k4] = v;
        }
        for (int q = t; q < 32 * 16; q += 256) {
            int k = q >> 4;
            int f4 = (q & 15) * 4;
            *(float4*)&sY1[k][f4] = *(const float4*)&y1[(k0 + k) * F + f4];
            *(float4*)&sY2[k][f4] = *(const float4*)&y2[(k0 + k) * F + f4];
        }
        __syncthreads();

#pragma unroll
        for (int kk = 0; kk < 8; kk++) {
            float a_[8][4];
#pragma unroll
            for (int ii = 0; ii < 8; ii++)
                *(float4*)a_[ii] = *(const float4*)&sA[ty * 8 + ii][kk * 4];
#pragma unroll
            for (int kq = 0; kq < 4; kq++) {
                int k = kk * 4 + kq;
                float4 b1 = *(const float4*)&sY1[k][tx * 4];
                float4 b2 = *(const float4*)&sY2[k][tx * 4];
                float b1v[4] = {b1.x, b1.y, b1.z, b1.w};
                float b2v[4] = {b2.x, b2.y, b2.z, b2.w};
#pragma unroll
                for (int ii = 0; ii < 8; ii++) {
                    float av = a_[ii][kq];
                    float a2 = av * av;
#pragma unroll
                    for (int jj = 0; jj < 4; jj++) {
                        acc[ii][jj] = fmaf(av, b1v[jj], acc[ii][jj]);
                        acc[ii][jj] = fmaf(a2, b2v[jj], acc[ii][jj]);
                    }
                }
            }
        }
        __syncthreads();
    }

    float* p = g_part + ks * YSZ + b * V * F;
#pragma unroll
    for (int ii = 0; ii < 8; ii++) {
        int row = i0 + ty * 8 + ii;
        *(float4*)&p[row * F + tx * 4] =
            make_float4(acc[ii][0], acc[ii][1], acc[ii][2], acc[ii][3]);
    }
}

// ---------------- stage 3: gcn = relu(Y0 + P0 + P1 + P2 + P3), final loss ----------------
__global__ void epilogue_kernel(float* __restrict__ gcn, float* __restrict__ out_loss) {
    int idx = blockIdx.x * 256 + threadIdx.x;  // float4 index, total YSZ/4
    if (idx == 0) {
        float acc = 0.f;
#pragma unroll
        for (int i = 0; i < NB * 4; i++) acc += g_lossP[i];
        *out_loss = acc;
    }
    float4 y = ((const float4*)g_Y)[idx];
    float4 p0 = ((const float4*)g_part)[idx];
    float4 p1 = ((const float4*)(g_part + YSZ))[idx];
    float4 p2 = ((const float4*)(g_part + 2 * YSZ))[idx];
    float4 p3 = ((const float4*)(g_part + 3 * YSZ))[idx];
    float4 o = make_float4(fmaxf(y.x + p0.x + p1.x + p2.x + p3.x, 0.f),
                           fmaxf(y.y + p0.y + p1.y + p2.y + p3.y, 0.f),
                           fmaxf(y.z + p0.z + p1.z + p2.z + p3.z, 0.f),
                           fmaxf(y.w + p0.w + p1.w + p2.w + p3.w, 0.f));
    ((float4*)gcn)[idx] = o;
}

// ---------------- launch ----------------
extern "C" void kernel_launch(void* const* d_in, const int* in_sizes, int n_in,
                              void* d_out, int out_size) {
    const float* x = (const float*)d_in[0];      // (64,256,64)
    const float* a = (const float*)d_in[1];      // (64,)
    const float* theta = (const float*)d_in[2];  // (3,64,64)

    float* out = (float*)d_out;
    float* gcn = out;                                 // NB*V*C
    float* s_out = out + (size_t)NB * V * C;          // NB*V*V
    float* loss = out + (size_t)NB * V * C + (size_t)NB * V * V;  // 1

    mega1_kernel<<<N_PW + N_YG, 256>>>(x, a, theta, s_out);

    dim3 gB(8, NB);
    fused_gemm_kernel<<<gB, 256>>>(s_out);

    epilogue_kernel<<<YSZ / 4 / 256, 256>>>(gcn, loss);
}